// round 2
// baseline (speedup 1.0000x reference)
#include <cuda_runtime.h>
#include <cstdint>

#define NN 50000
#define NE 800000

// ---------------- static device scratch (allocation-free rule) ----------------
// All vector-accessed arrays are float4-typed => 16B alignment guaranteed.
__device__ int    g_cnt[NN];
__device__ int    g_fill[NN];
__device__ int    g_rowptr[NN + 1];
__device__ float  g_invdeg[NN];
__device__ int    g_csr[NE];
__device__ float4 g_m  [(size_t)NN * 64];   // aggregated mean features (<=256 f/row)
__device__ float4 g_h  [(size_t)NN * 64];   // hidden activations
__device__ float4 g_pre[(size_t)NN * 64];   // pre-BN linear output
__device__ float  g_sum[256];
__device__ float  g_sumsq[256];
__device__ float4 g_scale[64];
__device__ float4 g_shift[64];

// ---------------- CSR build ----------------
__global__ void k_zero_cnt() {
    int i = blockIdx.x * blockDim.x + threadIdx.x;
    if (i < NN) { g_cnt[i] = 0; g_fill[i] = 0; }
}

__global__ void k_hist(const int* __restrict__ dst) {
    int e = blockIdx.x * blockDim.x + threadIdx.x;
    if (e < NE) atomicAdd(&g_cnt[dst[e]], 1);
}

__global__ void k_scan() {   // single block, 1024 threads: prefix sum over g_cnt
    __shared__ int sdata[1024];
    __shared__ int s_off;
    int tid = threadIdx.x;
    if (tid == 0) { s_off = 0; g_rowptr[0] = 0; }
    __syncthreads();
    for (int base = 0; base < NN; base += 1024) {
        int i = base + tid;
        int v = (i < NN) ? g_cnt[i] : 0;
        sdata[tid] = v;
        __syncthreads();
        for (int s = 1; s < 1024; s <<= 1) {
            int t = (tid >= s) ? sdata[tid - s] : 0;
            __syncthreads();
            sdata[tid] += t;
            __syncthreads();
        }
        int incl = sdata[tid];
        int off  = s_off;
        if (i < NN) {
            g_rowptr[i + 1] = off + incl;
            g_invdeg[i] = 1.0f / (float)max(v, 1);
        }
        __syncthreads();
        if (tid == 1023) s_off = off + incl;
        __syncthreads();
    }
}

__global__ void k_fill(const int* __restrict__ src, const int* __restrict__ dst) {
    int e = blockIdx.x * blockDim.x + threadIdx.x;
    if (e < NE) {
        int d = dst[e];
        int p = g_rowptr[d] + atomicAdd(&g_fill[d], 1);
        g_csr[p] = src[e];
    }
}

// ---------------- mean aggregation (CSR gather): g_m = mean_{src->node} h ----------------
template<int DIN, bool FROMX>
__global__ void k_agg(const float* __restrict__ xin) {
    const int TPN = DIN / 4;                 // float4 lanes per node
    int t = blockIdx.x * blockDim.x + threadIdx.x;
    int node = t / TPN;
    if (node >= NN) return;
    int c4 = t % TPN;
    const float4* __restrict__ h =
        FROMX ? reinterpret_cast<const float4*>(xin) : (const float4*)g_h;
    int beg = g_rowptr[node], end = g_rowptr[node + 1];
    float4 acc = make_float4(0.f, 0.f, 0.f, 0.f);
    #pragma unroll 4
    for (int e = beg; e < end; e++) {
        int s = g_csr[e];
        float4 v = h[(size_t)s * TPN + c4];
        acc.x += v.x; acc.y += v.y; acc.z += v.z; acc.w += v.w;
    }
    float inv = g_invdeg[node];
    acc.x *= inv; acc.y *= inv; acc.z *= inv; acc.w *= inv;
    g_m[(size_t)node * TPN + c4] = acc;
}

// ---------------- fused dual GEMM: g_pre = g_m*B1 + h*B2 + bias, + BN stats ----------------
__global__ void k_zero_stats() {
    int t = threadIdx.x;
    g_sum[t] = 0.f; g_sumsq[t] = 0.f;
}

template<int K, int DOUT, bool FROMX>
__global__ __launch_bounds__(256) void k_gemm(
    const float* __restrict__ xin,
    const float* __restrict__ B1w, const float* __restrict__ B2w,
    const float* __restrict__ bias)
{
    __shared__ float As[16][68];
    __shared__ float Bs[16][68];
    __shared__ float red[16][64];

    const int tid = threadIdx.x;
    const int tx = tid & 15, ty = tid >> 4;
    const int n0 = blockIdx.x * 64;
    const int m0 = blockIdx.y * 64;

    const int a_row = tid >> 2;          // 0..63
    const int a_col = (tid & 3) * 4;     // 0,4,8,12
    const int b_row = tid >> 4;          // 0..15
    const int b_col = (tid & 15) * 4;    // 0..60

    const float* A1 = (const float*)g_m;
    const float* A2 = FROMX ? xin : (const float*)g_h;
    float*       C  = (float*)g_pre;

    float c[4][4];
    #pragma unroll
    for (int i = 0; i < 4; i++)
        #pragma unroll
        for (int j = 0; j < 4; j++) c[i][j] = 0.f;

    #pragma unroll
    for (int phase = 0; phase < 2; phase++) {
        const float* __restrict__ A = phase ? A2 : A1;
        const float* __restrict__ B = phase ? B2w : B1w;
        for (int k0 = 0; k0 < K; k0 += 16) {
            int gr = m0 + a_row;
            float4 av = (gr < NN)
                ? *reinterpret_cast<const float4*>(A + (size_t)gr * K + k0 + a_col)
                : make_float4(0.f, 0.f, 0.f, 0.f);
            As[a_col + 0][a_row] = av.x;
            As[a_col + 1][a_row] = av.y;
            As[a_col + 2][a_row] = av.z;
            As[a_col + 3][a_row] = av.w;
            *reinterpret_cast<float4*>(&Bs[b_row][b_col]) =
                *reinterpret_cast<const float4*>(B + (size_t)(k0 + b_row) * DOUT + n0 + b_col);
            __syncthreads();
            #pragma unroll
            for (int kk = 0; kk < 16; kk++) {
                float ra[4], rb[4];
                #pragma unroll
                for (int i = 0; i < 4; i++) ra[i] = As[kk][ty * 4 + i];
                #pragma unroll
                for (int j = 0; j < 4; j++) rb[j] = Bs[kk][tx * 4 + j];
                #pragma unroll
                for (int i = 0; i < 4; i++)
                    #pragma unroll
                    for (int j = 0; j < 4; j++) c[i][j] += ra[i] * rb[j];
            }
            __syncthreads();
        }
    }

    // epilogue: bias, store, per-column sum & sumsq partials
    float bb[4];
    #pragma unroll
    for (int j = 0; j < 4; j++) bb[j] = bias[n0 + tx * 4 + j];

    float s[4] = {0.f, 0.f, 0.f, 0.f};
    float q[4] = {0.f, 0.f, 0.f, 0.f};
    #pragma unroll
    for (int i = 0; i < 4; i++) {
        int gr = m0 + ty * 4 + i;
        if (gr < NN) {
            float4 v;
            v.x = c[i][0] + bb[0];
            v.y = c[i][1] + bb[1];
            v.z = c[i][2] + bb[2];
            v.w = c[i][3] + bb[3];
            *reinterpret_cast<float4*>(C + (size_t)gr * DOUT + n0 + tx * 4) = v;
            s[0] += v.x; s[1] += v.y; s[2] += v.z; s[3] += v.w;
            q[0] += v.x * v.x; q[1] += v.y * v.y; q[2] += v.z * v.z; q[3] += v.w * v.w;
        }
    }
    #pragma unroll
    for (int j = 0; j < 4; j++) red[ty][tx * 4 + j] = s[j];
    __syncthreads();
    if (tid < 64) {
        float t = 0.f;
        #pragma unroll
        for (int r = 0; r < 16; r++) t += red[r][tid];
        atomicAdd(&g_sum[n0 + tid], t);
    }
    __syncthreads();
    #pragma unroll
    for (int j = 0; j < 4; j++) red[ty][tx * 4 + j] = q[j];
    __syncthreads();
    if (tid < 64) {
        float t = 0.f;
        #pragma unroll
        for (int r = 0; r < 16; r++) t += red[r][tid];
        atomicAdd(&g_sumsq[n0 + tid], t);
    }
}

// ---------------- BN finalize + apply ----------------
template<int DOUT>
__global__ void k_bnfin(const float* __restrict__ gamma, const float* __restrict__ beta) {
    int cidx = threadIdx.x;
    if (cidx < DOUT) {
        float mu  = g_sum[cidx] * (1.0f / NN);
        float var = g_sumsq[cidx] * (1.0f / NN) - mu * mu;
        float sc  = gamma[cidx] * rsqrtf(var + 1e-5f);
        ((float*)g_scale)[cidx] = sc;
        ((float*)g_shift)[cidx] = beta[cidx] - mu * sc;
    }
}

template<bool RELU, int DOUT, bool TOOUT>
__global__ void k_bnapply(float* __restrict__ outp) {
    const int total = NN * (DOUT / 4);
    int i = blockIdx.x * blockDim.x + threadIdx.x;
    if (i >= total) return;
    int c4 = i % (DOUT / 4);
    float4 v  = g_pre[i];
    float4 sc = g_scale[c4];
    float4 sh = g_shift[c4];
    v.x = v.x * sc.x + sh.x;
    v.y = v.y * sc.y + sh.y;
    v.z = v.z * sc.z + sh.z;
    v.w = v.w * sc.w + sh.w;
    if (RELU) {
        v.x = fmaxf(v.x, 0.f); v.y = fmaxf(v.y, 0.f);
        v.z = fmaxf(v.z, 0.f); v.w = fmaxf(v.w, 0.f);
    }
    if (TOOUT) reinterpret_cast<float4*>(outp)[i] = v;
    else       g_h[i] = v;
}

// ---------------- launch ----------------
extern "C" void kernel_launch(void* const* d_in, const int* in_sizes, int n_in,
                              void* d_out, int out_size) {
    const float* x    = (const float*)d_in[0];
    const int*   ei   = (const int*)d_in[1];
    const int*   esrc = ei;
    const int*   edst = ei + NE;
    const float* wn0 = (const float*)d_in[2];
    const float* ws0 = (const float*)d_in[3];
    const float* b0  = (const float*)d_in[4];
    const float* g0  = (const float*)d_in[5];
    const float* be0 = (const float*)d_in[6];
    const float* wn1 = (const float*)d_in[7];
    const float* ws1 = (const float*)d_in[8];
    const float* b1  = (const float*)d_in[9];
    const float* g1  = (const float*)d_in[10];
    const float* be1 = (const float*)d_in[11];
    const float* wn2 = (const float*)d_in[12];
    const float* ws2 = (const float*)d_in[13];
    const float* b2  = (const float*)d_in[14];
    const float* g2  = (const float*)d_in[15];
    const float* be2 = (const float*)d_in[16];
    float* out = (float*)d_out;

    // CSR build (reused by all 3 layers)
    k_zero_cnt<<<(NN + 255) / 256, 256>>>();
    k_hist<<<(NE + 255) / 256, 256>>>(edst);
    k_scan<<<1, 1024>>>();
    k_fill<<<(NE + 255) / 256, 256>>>(esrc, edst);

    const int M_TILES = (NN + 63) / 64;

    // ---- layer 0: 128 -> 256 ----
    k_agg<128, true><<<(NN * 32 + 255) / 256, 256>>>(x);
    k_zero_stats<<<1, 256>>>();
    k_gemm<128, 256, true><<<dim3(4, M_TILES), 256>>>(x, wn0, ws0, b0);
    k_bnfin<256><<<1, 256>>>(g0, be0);
    k_bnapply<true, 256, false><<<(NN * 64 + 255) / 256, 256>>>(nullptr);

    // ---- layer 1: 256 -> 256 ----
    k_agg<256, false><<<(NN * 64 + 255) / 256, 256>>>(nullptr);
    k_zero_stats<<<1, 256>>>();
    k_gemm<256, 256, false><<<dim3(4, M_TILES), 256>>>(nullptr, wn1, ws1, b1);
    k_bnfin<256><<<1, 256>>>(g1, be1);
    k_bnapply<true, 256, false><<<(NN * 64 + 255) / 256, 256>>>(nullptr);

    // ---- layer 2: 256 -> 128 ----
    k_agg<256, false><<<(NN * 64 + 255) / 256, 256>>>(nullptr);
    k_zero_stats<<<1, 256>>>();
    k_gemm<256, 128, false><<<dim3(2, M_TILES), 256>>>(nullptr, wn2, ws2, b2);
    k_bnfin<128><<<1, 256>>>(g2, be2);
    k_bnapply<false, 128, true><<<(NN * 32 + 255) / 256, 256>>>(out);
}

// round 3
// speedup vs baseline: 1.1155x; 1.1155x over previous
#include <cuda_runtime.h>
#include <cstdint>

#define NN 50000
#define NE 800000

// ---------------- static device scratch ----------------
__device__ int    g_cnt[NN];
__device__ int    g_fill[NN];
__device__ int    g_rowptr[NN + 1];
__device__ float  g_invdeg[NN];
__device__ int    g_csr[NE];
__device__ float4 g_m  [(size_t)NN * 64];
__device__ float4 g_h  [(size_t)NN * 64];
__device__ float4 g_pre[(size_t)NN * 64];
__device__ float  g_sum[768];     // 3 layers x 256
__device__ float  g_sumsq[768];
__device__ float4 g_scale[64];
__device__ float4 g_shift[64];

// ---------------- packed fp32 helpers ----------------
__device__ __forceinline__ unsigned long long dup2(float x) {
    unsigned long long r;
    asm("mov.b64 %0, {%1, %1};" : "=l"(r) : "f"(x));
    return r;
}
__device__ __forceinline__ void ffma2(unsigned long long& c,
                                      unsigned long long a, unsigned long long b) {
    asm("fma.rn.f32x2 %0, %1, %2, %0;" : "+l"(c) : "l"(a), "l"(b));
}
__device__ __forceinline__ void unpack2(unsigned long long v, float& lo, float& hi) {
    asm("mov.b64 {%0, %1}, %2;" : "=f"(lo), "=f"(hi) : "l"(v));
}

// ---------------- CSR build ----------------
__global__ void k_zero_cnt() {
    int i = blockIdx.x * blockDim.x + threadIdx.x;
    if (i < NN) { g_cnt[i] = 0; g_fill[i] = 0; }
    if (i < 768) { g_sum[i] = 0.f; g_sumsq[i] = 0.f; }
}

__global__ void k_hist(const int* __restrict__ dst) {
    int e = blockIdx.x * blockDim.x + threadIdx.x;
    if (e < NE) atomicAdd(&g_cnt[dst[e]], 1);
}

__global__ void k_scan() {   // single block, 1024 threads, shuffle-based
    __shared__ int wsum[32];
    __shared__ int s_off;
    const int tid  = threadIdx.x;
    const int lane = tid & 31;
    const int wid  = tid >> 5;
    if (tid == 0) { s_off = 0; g_rowptr[0] = 0; }
    __syncthreads();
    for (int base = 0; base < NN; base += 1024) {
        int i = base + tid;
        int v = (i < NN) ? g_cnt[i] : 0;
        int x = v;
        #pragma unroll
        for (int d = 1; d < 32; d <<= 1) {
            int t = __shfl_up_sync(0xffffffffu, x, d);
            if (lane >= d) x += t;
        }
        if (lane == 31) wsum[wid] = x;
        __syncthreads();
        if (wid == 0) {
            int w = wsum[lane];
            #pragma unroll
            for (int d = 1; d < 32; d <<= 1) {
                int t = __shfl_up_sync(0xffffffffu, w, d);
                if (lane >= d) w += t;
            }
            wsum[lane] = w;
        }
        __syncthreads();
        int incl = x + (wid ? wsum[wid - 1] : 0);
        int off  = s_off;
        if (i < NN) {
            g_rowptr[i + 1] = off + incl;
            g_invdeg[i] = 1.0f / (float)max(v, 1);
        }
        __syncthreads();
        if (tid == 1023) s_off = off + incl;
        __syncthreads();
    }
}

__global__ void k_fill(const int* __restrict__ src, const int* __restrict__ dst) {
    int e = blockIdx.x * blockDim.x + threadIdx.x;
    if (e < NE) {
        int d = dst[e];
        int p = g_rowptr[d] + atomicAdd(&g_fill[d], 1);
        g_csr[p] = src[e];
    }
}

// ---------------- mean aggregation ----------------
template<int DIN, bool FROMX>
__global__ void k_agg(const float* __restrict__ xin) {
    const int TPN = DIN / 4;
    int t = blockIdx.x * blockDim.x + threadIdx.x;
    int node = t / TPN;
    if (node >= NN) return;
    int c4 = t % TPN;
    const float4* __restrict__ h =
        FROMX ? reinterpret_cast<const float4*>(xin) : (const float4*)g_h;
    int beg = g_rowptr[node], end = g_rowptr[node + 1];
    float4 acc = make_float4(0.f, 0.f, 0.f, 0.f);
    #pragma unroll 4
    for (int e = beg; e < end; e++) {
        int s = g_csr[e];
        float4 v = h[(size_t)s * TPN + c4];
        acc.x += v.x; acc.y += v.y; acc.z += v.z; acc.w += v.w;
    }
    float inv = g_invdeg[node];
    acc.x *= inv; acc.y *= inv; acc.z *= inv; acc.w *= inv;
    g_m[(size_t)node * TPN + c4] = acc;
}

// ---------------- fused dual GEMM (128x64 tile, FFMA2) + BN stats ----------------
template<int K, int DOUT, bool FROMX>
__global__ __launch_bounds__(256) void k_gemm(
    const float* __restrict__ xin,
    const float* __restrict__ B1w, const float* __restrict__ B2w,
    const float* __restrict__ bias, int layer)
{
    __shared__ float As[16][132];   // [k][m], row stride 528B (16B mult)
    __shared__ float Bs[16][68];    // [k][n], row stride 272B (16B mult)
    __shared__ float red[16][64];

    const int tid = threadIdx.x;
    const int tx = tid & 15, ty = tid >> 4;
    const int n0 = blockIdx.x * 64;
    const int m0 = blockIdx.y * 128;

    const int a_row = tid >> 1;          // 0..127
    const int a_col = (tid & 1) * 8;     // 0 or 8
    const int b_row = tid >> 4;          // 0..15
    const int b_col = (tid & 15) * 4;

    const float* A1 = (const float*)g_m;
    const float* A2 = FROMX ? xin : (const float*)g_h;
    float*       C  = (float*)g_pre;

    unsigned long long c2[8][2];
    #pragma unroll
    for (int i = 0; i < 8; i++) { c2[i][0] = 0ull; c2[i][1] = 0ull; }

    #pragma unroll
    for (int phase = 0; phase < 2; phase++) {
        const float* __restrict__ A = phase ? A2 : A1;
        const float* __restrict__ B = phase ? B2w : B1w;
        for (int k0 = 0; k0 < K; k0 += 16) {
            const int gr = m0 + a_row;
            float4 av0, av1;
            if (gr < NN) {
                av0 = *reinterpret_cast<const float4*>(A + (size_t)gr * K + k0 + a_col);
                av1 = *reinterpret_cast<const float4*>(A + (size_t)gr * K + k0 + a_col + 4);
            } else {
                av0 = make_float4(0.f, 0.f, 0.f, 0.f);
                av1 = av0;
            }
            As[a_col + 0][a_row] = av0.x;
            As[a_col + 1][a_row] = av0.y;
            As[a_col + 2][a_row] = av0.z;
            As[a_col + 3][a_row] = av0.w;
            As[a_col + 4][a_row] = av1.x;
            As[a_col + 5][a_row] = av1.y;
            As[a_col + 6][a_row] = av1.z;
            As[a_col + 7][a_row] = av1.w;
            *reinterpret_cast<float4*>(&Bs[b_row][b_col]) =
                *reinterpret_cast<const float4*>(B + (size_t)(k0 + b_row) * DOUT + n0 + b_col);
            __syncthreads();
            #pragma unroll
            for (int kk = 0; kk < 16; kk++) {
                float4 p = *reinterpret_cast<const float4*>(&As[kk][ty * 8]);
                float4 q = *reinterpret_cast<const float4*>(&As[kk][ty * 8 + 4]);
                unsigned long long rb0 =
                    *reinterpret_cast<const unsigned long long*>(&Bs[kk][tx * 4]);
                unsigned long long rb1 =
                    *reinterpret_cast<const unsigned long long*>(&Bs[kk][tx * 4 + 2]);
                float ra[8] = {p.x, p.y, p.z, p.w, q.x, q.y, q.z, q.w};
                #pragma unroll
                for (int i = 0; i < 8; i++) {
                    unsigned long long ai = dup2(ra[i]);
                    ffma2(c2[i][0], ai, rb0);
                    ffma2(c2[i][1], ai, rb1);
                }
            }
            __syncthreads();
        }
    }

    // epilogue: unpack, bias, store, per-column BN partial sums
    float bb[4];
    #pragma unroll
    for (int j = 0; j < 4; j++) bb[j] = bias[n0 + tx * 4 + j];

    float s[4] = {0.f, 0.f, 0.f, 0.f};
    float q2[4] = {0.f, 0.f, 0.f, 0.f};
    #pragma unroll
    for (int i = 0; i < 8; i++) {
        int gr = m0 + ty * 8 + i;
        if (gr < NN) {
            float v0, v1, v2, v3;
            unpack2(c2[i][0], v0, v1);
            unpack2(c2[i][1], v2, v3);
            float4 v;
            v.x = v0 + bb[0]; v.y = v1 + bb[1];
            v.z = v2 + bb[2]; v.w = v3 + bb[3];
            *reinterpret_cast<float4*>(C + (size_t)gr * DOUT + n0 + tx * 4) = v;
            s[0] += v.x; s[1] += v.y; s[2] += v.z; s[3] += v.w;
            q2[0] += v.x * v.x; q2[1] += v.y * v.y;
            q2[2] += v.z * v.z; q2[3] += v.w * v.w;
        }
    }
    #pragma unroll
    for (int j = 0; j < 4; j++) red[ty][tx * 4 + j] = s[j];
    __syncthreads();
    if (tid < 64) {
        float t = 0.f;
        #pragma unroll
        for (int r = 0; r < 16; r++) t += red[r][tid];
        atomicAdd(&g_sum[layer * 256 + n0 + tid], t);
    }
    __syncthreads();
    #pragma unroll
    for (int j = 0; j < 4; j++) red[ty][tx * 4 + j] = q2[j];
    __syncthreads();
    if (tid < 64) {
        float t = 0.f;
        #pragma unroll
        for (int r = 0; r < 16; r++) t += red[r][tid];
        atomicAdd(&g_sumsq[layer * 256 + n0 + tid], t);
    }
}

// ---------------- BN finalize + apply ----------------
template<int DOUT>
__global__ void k_bnfin(const float* __restrict__ gamma, const float* __restrict__ beta,
                        int layer) {
    int cidx = threadIdx.x;
    if (cidx < DOUT) {
        float mu  = g_sum[layer * 256 + cidx] * (1.0f / NN);
        float var = g_sumsq[layer * 256 + cidx] * (1.0f / NN) - mu * mu;
        float sc  = gamma[cidx] * rsqrtf(var + 1e-5f);
        ((float*)g_scale)[cidx] = sc;
        ((float*)g_shift)[cidx] = beta[cidx] - mu * sc;
    }
}

template<bool RELU, int DOUT, bool TOOUT>
__global__ void k_bnapply(float* __restrict__ outp) {
    const int total = NN * (DOUT / 4);
    int i = blockIdx.x * blockDim.x + threadIdx.x;
    if (i >= total) return;
    int c4 = i % (DOUT / 4);
    float4 v  = g_pre[i];
    float4 sc = g_scale[c4];
    float4 sh = g_shift[c4];
    v.x = v.x * sc.x + sh.x;
    v.y = v.y * sc.y + sh.y;
    v.z = v.z * sc.z + sh.z;
    v.w = v.w * sc.w + sh.w;
    if (RELU) {
        v.x = fmaxf(v.x, 0.f); v.y = fmaxf(v.y, 0.f);
        v.z = fmaxf(v.z, 0.f); v.w = fmaxf(v.w, 0.f);
    }
    if (TOOUT) reinterpret_cast<float4*>(outp)[i] = v;
    else       g_h[i] = v;
}

// ---------------- launch ----------------
extern "C" void kernel_launch(void* const* d_in, const int* in_sizes, int n_in,
                              void* d_out, int out_size) {
    const float* x    = (const float*)d_in[0];
    const int*   ei   = (const int*)d_in[1];
    const int*   esrc = ei;
    const int*   edst = ei + NE;
    const float* wn0 = (const float*)d_in[2];
    const float* ws0 = (const float*)d_in[3];
    const float* b0  = (const float*)d_in[4];
    const float* g0  = (const float*)d_in[5];
    const float* be0 = (const float*)d_in[6];
    const float* wn1 = (const float*)d_in[7];
    const float* ws1 = (const float*)d_in[8];
    const float* b1  = (const float*)d_in[9];
    const float* g1  = (const float*)d_in[10];
    const float* be1 = (const float*)d_in[11];
    const float* wn2 = (const float*)d_in[12];
    const float* ws2 = (const float*)d_in[13];
    const float* b2  = (const float*)d_in[14];
    const float* g2  = (const float*)d_in[15];
    const float* be2 = (const float*)d_in[16];
    float* out = (float*)d_out;

    k_zero_cnt<<<(NN + 255) / 256, 256>>>();
    k_hist<<<(NE + 255) / 256, 256>>>(edst);
    k_scan<<<1, 1024>>>();
    k_fill<<<(NE + 255) / 256, 256>>>(esrc, edst);

    const int M_TILES = (NN + 127) / 128;

    // ---- layer 0: 128 -> 256 ----
    k_agg<128, true><<<(NN * 32 + 255) / 256, 256>>>(x);
    k_gemm<128, 256, true><<<dim3(4, M_TILES), 256>>>(x, wn0, ws0, b0, 0);
    k_bnfin<256><<<1, 256>>>(g0, be0, 0);
    k_bnapply<true, 256, false><<<(NN * 64 + 255) / 256, 256>>>(nullptr);

    // ---- layer 1: 256 -> 256 ----
    k_agg<256, false><<<(NN * 64 + 255) / 256, 256>>>(nullptr);
    k_gemm<256, 256, false><<<dim3(4, M_TILES), 256>>>(nullptr, wn1, ws1, b1, 1);
    k_bnfin<256><<<1, 256>>>(g1, be1, 1);
    k_bnapply<true, 256, false><<<(NN * 64 + 255) / 256, 256>>>(nullptr);

    // ---- layer 2: 256 -> 128 ----
    k_agg<256, false><<<(NN * 64 + 255) / 256, 256>>>(nullptr);
    k_gemm<256, 128, false><<<dim3(2, M_TILES), 256>>>(nullptr, wn2, ws2, b2, 2);
    k_bnfin<128><<<1, 256>>>(g2, be2, 2);
    k_bnapply<false, 128, true><<<(NN * 32 + 255) / 256, 256>>>(out);
}

// round 5
// speedup vs baseline: 1.5887x; 1.4242x over previous
#include <cuda_runtime.h>
#include <cstdint>

#define NN 50000
#define NE 800000

// ---------------- static device scratch ----------------
__device__ int    g_cnt[NN];
__device__ int    g_fill[NN];
__device__ int    g_rowptr[NN + 1];
__device__ float  g_invdeg[NN];
__device__ int    g_csr[NE];
__device__ float4 g_m  [(size_t)NN * 64];
__device__ float4 g_h  [(size_t)NN * 64];
__device__ float4 g_pre[(size_t)NN * 64];
__device__ float  g_sum[768];     // 3 layers x 256
__device__ float  g_sumsq[768];
__device__ float4 g_scale[64];
__device__ float4 g_shift[64];

// ---------------- helpers ----------------
__device__ __forceinline__ float to_tf32(float x) {
    unsigned r;
    asm("cvt.rna.tf32.f32 %0, %1;" : "=r"(r) : "f"(x));
    return __uint_as_float(r);
}
__device__ __forceinline__ void mma_tf32(float* c, const unsigned* a, const unsigned* b) {
    asm("mma.sync.aligned.m16n8k8.row.col.f32.tf32.tf32.f32 "
        "{%0,%1,%2,%3}, {%4,%5,%6,%7}, {%8,%9}, {%0,%1,%2,%3};"
        : "+f"(c[0]), "+f"(c[1]), "+f"(c[2]), "+f"(c[3])
        : "r"(a[0]), "r"(a[1]), "r"(a[2]), "r"(a[3]),
          "r"(b[0]), "r"(b[1]));
}

// ---------------- CSR build ----------------
__global__ void k_zero_cnt() {
    int i = blockIdx.x * blockDim.x + threadIdx.x;
    if (i < NN) { g_cnt[i] = 0; g_fill[i] = 0; }
    if (i < 768) { g_sum[i] = 0.f; g_sumsq[i] = 0.f; }
}

__global__ void k_hist(const int* __restrict__ dst) {
    int e = blockIdx.x * blockDim.x + threadIdx.x;
    if (e < NE) atomicAdd(&g_cnt[dst[e]], 1);
}

__global__ void k_scan() {   // single block, 1024 threads, shuffle-based
    __shared__ int wsum[32];
    __shared__ int s_off;
    const int tid  = threadIdx.x;
    const int lane = tid & 31;
    const int wid  = tid >> 5;
    if (tid == 0) { s_off = 0; g_rowptr[0] = 0; }
    __syncthreads();
    for (int base = 0; base < NN; base += 1024) {
        int i = base + tid;
        int v = (i < NN) ? g_cnt[i] : 0;
        int x = v;
        #pragma unroll
        for (int d = 1; d < 32; d <<= 1) {
            int t = __shfl_up_sync(0xffffffffu, x, d);
            if (lane >= d) x += t;
        }
        if (lane == 31) wsum[wid] = x;
        __syncthreads();
        if (wid == 0) {
            int w = wsum[lane];
            #pragma unroll
            for (int d = 1; d < 32; d <<= 1) {
                int t = __shfl_up_sync(0xffffffffu, w, d);
                if (lane >= d) w += t;
            }
            wsum[lane] = w;
        }
        __syncthreads();
        int incl = x + (wid ? wsum[wid - 1] : 0);
        int off  = s_off;
        if (i < NN) {
            g_rowptr[i + 1] = off + incl;
            g_invdeg[i] = 1.0f / (float)max(v, 1);
        }
        __syncthreads();
        if (tid == 1023) s_off = off + incl;
        __syncthreads();
    }
}

__global__ void k_fill(const int* __restrict__ src, const int* __restrict__ dst) {
    int e = blockIdx.x * blockDim.x + threadIdx.x;
    if (e < NE) {
        int d = dst[e];
        int p = g_rowptr[d] + atomicAdd(&g_fill[d], 1);
        g_csr[p] = src[e];
    }
}

// ---------------- mean aggregation ----------------
template<int DIN, bool FROMX>
__global__ void k_agg(const float* __restrict__ xin) {
    const int TPN = DIN / 4;
    int t = blockIdx.x * blockDim.x + threadIdx.x;
    int node = t / TPN;
    if (node >= NN) return;
    int c4 = t % TPN;
    const float4* __restrict__ h =
        FROMX ? reinterpret_cast<const float4*>(xin) : (const float4*)g_h;
    int beg = g_rowptr[node], end = g_rowptr[node + 1];
    float4 acc = make_float4(0.f, 0.f, 0.f, 0.f);
    #pragma unroll 4
    for (int e = beg; e < end; e++) {
        int s = g_csr[e];
        float4 v = h[(size_t)s * TPN + c4];
        acc.x += v.x; acc.y += v.y; acc.z += v.z; acc.w += v.w;
    }
    float inv = g_invdeg[node];
    acc.x *= inv; acc.y *= inv; acc.z *= inv; acc.w *= inv;
    g_m[(size_t)node * TPN + c4] = acc;
}

// ---------------- fused dual GEMM (TF32 tensor cores) + BN stats ----------------
// Block tile 128(M) x 64(N), 256 threads = 8 warps in 4x2, warp tile 32x32.
template<int K, int DOUT, bool FROMX>
__global__ __launch_bounds__(256) void k_gemm(
    const float* __restrict__ xin,
    const float* __restrict__ B1w, const float* __restrict__ B2w,
    const float* __restrict__ bias, int layer)
{
    __shared__ float As[128 * 20];   // [m][k], stride 20 (pad vs bank conflicts)
    __shared__ float Bs[16 * 68];    // [k][n], stride 68

    const int tid    = threadIdx.x;
    const int lane   = tid & 31;
    const int wid    = tid >> 5;
    const int warp_m = wid >> 1;        // 0..3
    const int warp_n = wid & 1;         // 0..1
    const int mbase  = warp_m * 32;
    const int nbase  = warp_n * 32;
    const int n0 = blockIdx.x * 64;
    const int m0 = blockIdx.y * 128;

    const int a_row = tid >> 1;          // 0..127
    const int a_col = (tid & 1) * 8;     // 0 or 8
    const int b_row = tid >> 4;          // 0..15
    const int b_col = (tid & 15) * 4;

    const float* A1 = (const float*)g_m;
    const float* A2 = FROMX ? xin : (const float*)g_h;
    float*       C  = (float*)g_pre;

    float acc[2][4][4];
    #pragma unroll
    for (int i = 0; i < 2; i++)
        #pragma unroll
        for (int j = 0; j < 4; j++)
            #pragma unroll
            for (int r = 0; r < 4; r++) acc[i][j][r] = 0.f;

    #pragma unroll
    for (int phase = 0; phase < 2; phase++) {
        const float* __restrict__ A = phase ? A2 : A1;
        const float* __restrict__ B = phase ? B2w : B1w;
        for (int k0 = 0; k0 < K; k0 += 16) {
            // stage A tile [128 x 16] (tf32-rounded)
            const int gr = m0 + a_row;
            float4 av0, av1;
            if (gr < NN) {
                av0 = *reinterpret_cast<const float4*>(A + (size_t)gr * K + k0 + a_col);
                av1 = *reinterpret_cast<const float4*>(A + (size_t)gr * K + k0 + a_col + 4);
            } else {
                av0 = make_float4(0.f, 0.f, 0.f, 0.f);
                av1 = av0;
            }
            float* ap = &As[a_row * 20 + a_col];
            ap[0] = to_tf32(av0.x); ap[1] = to_tf32(av0.y);
            ap[2] = to_tf32(av0.z); ap[3] = to_tf32(av0.w);
            ap[4] = to_tf32(av1.x); ap[5] = to_tf32(av1.y);
            ap[6] = to_tf32(av1.z); ap[7] = to_tf32(av1.w);
            // stage B tile [16 x 64]
            float4 bv = *reinterpret_cast<const float4*>(
                B + (size_t)(k0 + b_row) * DOUT + n0 + b_col);
            float* bp = &Bs[b_row * 68 + b_col];
            bp[0] = to_tf32(bv.x); bp[1] = to_tf32(bv.y);
            bp[2] = to_tf32(bv.z); bp[3] = to_tf32(bv.w);
            __syncthreads();

            const unsigned* Asu = (const unsigned*)As;
            const unsigned* Bsu = (const unsigned*)Bs;
            #pragma unroll
            for (int ks = 0; ks < 16; ks += 8) {
                unsigned af[2][4], bf[4][2];
                #pragma unroll
                for (int sm = 0; sm < 2; sm++) {
                    int r = mbase + sm * 16 + (lane >> 2);
                    int kk = ks + (lane & 3);
                    af[sm][0] = Asu[r * 20 + kk];
                    af[sm][1] = Asu[(r + 8) * 20 + kk];
                    af[sm][2] = Asu[r * 20 + kk + 4];
                    af[sm][3] = Asu[(r + 8) * 20 + kk + 4];
                }
                #pragma unroll
                for (int sn = 0; sn < 4; sn++) {
                    int cc = nbase + sn * 8 + (lane >> 2);
                    int kb = ks + (lane & 3);
                    bf[sn][0] = Bsu[kb * 68 + cc];
                    bf[sn][1] = Bsu[(kb + 4) * 68 + cc];
                }
                #pragma unroll
                for (int sm = 0; sm < 2; sm++)
                    #pragma unroll
                    for (int sn = 0; sn < 4; sn++)
                        mma_tf32(acc[sm][sn], af[sm], bf[sn]);
            }
            __syncthreads();
        }
    }

    // ---------------- epilogue: bias + store + BN partial sums ----------------
    #pragma unroll
    for (int sn = 0; sn < 4; sn++) {
        const int colg = n0 + nbase + sn * 8 + 2 * (lane & 3);
        const float bb0 = bias[colg];
        const float bb1 = bias[colg + 1];
        float s0 = 0.f, s1 = 0.f, q0 = 0.f, q1 = 0.f;
        #pragma unroll
        for (int sm = 0; sm < 2; sm++) {
            const int r0 = m0 + mbase + sm * 16 + (lane >> 2);
            const int r1 = r0 + 8;
            float v0 = acc[sm][sn][0] + bb0;
            float v1 = acc[sm][sn][1] + bb1;
            float v2 = acc[sm][sn][2] + bb0;
            float v3 = acc[sm][sn][3] + bb1;
            if (r0 < NN) {
                *reinterpret_cast<float2*>(C + (size_t)r0 * DOUT + colg) =
                    make_float2(v0, v1);
                s0 += v0; q0 += v0 * v0;
                s1 += v1; q1 += v1 * v1;
            }
            if (r1 < NN) {
                *reinterpret_cast<float2*>(C + (size_t)r1 * DOUT + colg) =
                    make_float2(v2, v3);
                s0 += v2; q0 += v2 * v2;
                s1 += v3; q1 += v3 * v3;
            }
        }
        // reduce across lanes sharing the same (lane & 3): strides 16, 8, 4
        #pragma unroll
        for (int d = 16; d >= 4; d >>= 1) {
            s0 += __shfl_down_sync(0xffffffffu, s0, d);
            s1 += __shfl_down_sync(0xffffffffu, s1, d);
            q0 += __shfl_down_sync(0xffffffffu, q0, d);
            q1 += __shfl_down_sync(0xffffffffu, q1, d);
        }
        if (lane < 4) {
            const int cg = n0 + nbase + sn * 8 + 2 * lane;
            atomicAdd(&g_sum  [layer * 256 + cg],     s0);
            atomicAdd(&g_sum  [layer * 256 + cg + 1], s1);
            atomicAdd(&g_sumsq[layer * 256 + cg],     q0);
            atomicAdd(&g_sumsq[layer * 256 + cg + 1], q1);
        }
    }
}

// ---------------- BN finalize + apply ----------------
template<int DOUT>
__global__ void k_bnfin(const float* __restrict__ gamma, const float* __restrict__ beta,
                        int layer) {
    int cidx = threadIdx.x;
    if (cidx < DOUT) {
        float mu  = g_sum[layer * 256 + cidx] * (1.0f / NN);
        float var = g_sumsq[layer * 256 + cidx] * (1.0f / NN) - mu * mu;
        float sc  = gamma[cidx] * rsqrtf(var + 1e-5f);
        ((float*)g_scale)[cidx] = sc;
        ((float*)g_shift)[cidx] = beta[cidx] - mu * sc;
    }
}

template<bool RELU, int DOUT, bool TOOUT>
__global__ void k_bnapply(float* __restrict__ outp) {
    const int total = NN * (DOUT / 4);
    int i = blockIdx.x * blockDim.x + threadIdx.x;
    if (i >= total) return;
    int c4 = i % (DOUT / 4);
    float4 v  = g_pre[i];
    float4 sc = g_scale[c4];
    float4 sh = g_shift[c4];
    v.x = v.x * sc.x + sh.x;
    v.y = v.y * sc.y + sh.y;
    v.z = v.z * sc.z + sh.z;
    v.w = v.w * sc.w + sh.w;
    if (RELU) {
        v.x = fmaxf(v.x, 0.f); v.y = fmaxf(v.y, 0.f);
        v.z = fmaxf(v.z, 0.f); v.w = fmaxf(v.w, 0.f);
    }
    if (TOOUT) reinterpret_cast<float4*>(outp)[i] = v;
    else       g_h[i] = v;
}

// ---------------- launch ----------------
extern "C" void kernel_launch(void* const* d_in, const int* in_sizes, int n_in,
                              void* d_out, int out_size) {
    const float* x    = (const float*)d_in[0];
    const int*   ei   = (const int*)d_in[1];
    const int*   esrc = ei;
    const int*   edst = ei + NE;
    const float* wn0 = (const float*)d_in[2];
    const float* ws0 = (const float*)d_in[3];
    const float* b0  = (const float*)d_in[4];
    const float* g0  = (const float*)d_in[5];
    const float* be0 = (const float*)d_in[6];
    const float* wn1 = (const float*)d_in[7];
    const float* ws1 = (const float*)d_in[8];
    const float* b1  = (const float*)d_in[9];
    const float* g1  = (const float*)d_in[10];
    const float* be1 = (const float*)d_in[11];
    const float* wn2 = (const float*)d_in[12];
    const float* ws2 = (const float*)d_in[13];
    const float* b2  = (const float*)d_in[14];
    const float* g2  = (const float*)d_in[15];
    const float* be2 = (const float*)d_in[16];
    float* out = (float*)d_out;

    k_zero_cnt<<<(NN + 255) / 256, 256>>>();
    k_hist<<<(NE + 255) / 256, 256>>>(edst);
    k_scan<<<1, 1024>>>();
    k_fill<<<(NE + 255) / 256, 256>>>(esrc, edst);

    const int M_TILES = (NN + 127) / 128;

    // ---- layer 0: 128 -> 256 ----
    k_agg<128, true><<<(NN * 32 + 255) / 256, 256>>>(x);
    k_gemm<128, 256, true><<<dim3(4, M_TILES), 256>>>(x, wn0, ws0, b0, 0);
    k_bnfin<256><<<1, 256>>>(g0, be0, 0);
    k_bnapply<true, 256, false><<<(NN * 64 + 255) / 256, 256>>>(nullptr);

    // ---- layer 1: 256 -> 256 ----
    k_agg<256, false><<<(NN * 64 + 255) / 256, 256>>>(nullptr);
    k_gemm<256, 256, false><<<dim3(4, M_TILES), 256>>>(nullptr, wn1, ws1, b1, 1);
    k_bnfin<256><<<1, 256>>>(g1, be1, 1);
    k_bnapply<true, 256, false><<<(NN * 64 + 255) / 256, 256>>>(nullptr);

    // ---- layer 2: 256 -> 128 ----
    k_agg<256, false><<<(NN * 64 + 255) / 256, 256>>>(nullptr);
    k_gemm<256, 128, false><<<dim3(2, M_TILES), 256>>>(nullptr, wn2, ws2, b2, 2);
    k_bnfin<128><<<1, 256>>>(g2, be2, 2);
    k_bnapply<false, 128, true><<<(NN * 32 + 255) / 256, 256>>>(out);
}

// round 6
// speedup vs baseline: 1.9017x; 1.1970x over previous
#include <cuda_runtime.h>
#include <cuda_fp16.h>
#include <cstdint>

#define NN 50000
#define NE 800000

// ---------------- static device scratch ----------------
__device__ int    g_cnt[NN];
__device__ int    g_fill[NN];
__device__ int    g_rowptr[NN + 1];
__device__ float  g_invdeg[NN];
__device__ int    g_csr[NE];
__device__ uint4  g_xh[(size_t)NN * 16];   // x as fp16 (128 cols = 16 uint4)
__device__ uint4  g_hh[(size_t)NN * 32];   // hidden activations fp16 (<=256 cols)
__device__ uint4  g_mh[(size_t)NN * 32];   // aggregated mean fp16
__device__ float4 g_pre[(size_t)NN * 64];  // pre-BN linear output fp32
__device__ float  g_sum[768];              // 3 layers x 256
__device__ float  g_sumsq[768];
__device__ float4 g_scale[64];
__device__ float4 g_shift[64];

// ---------------- helpers ----------------
__device__ __forceinline__ float to_tf32(float x) {
    unsigned r;
    asm("cvt.rna.tf32.f32 %0, %1;" : "=r"(r) : "f"(x));
    return __uint_as_float(r);
}
__device__ __forceinline__ void mma_tf32(float* c, const unsigned* a, const unsigned* b) {
    asm("mma.sync.aligned.m16n8k8.row.col.f32.tf32.tf32.f32 "
        "{%0,%1,%2,%3}, {%4,%5,%6,%7}, {%8,%9}, {%0,%1,%2,%3};"
        : "+f"(c[0]), "+f"(c[1]), "+f"(c[2]), "+f"(c[3])
        : "r"(a[0]), "r"(a[1]), "r"(a[2]), "r"(a[3]),
          "r"(b[0]), "r"(b[1]));
}

// ---------------- CSR build ----------------
__global__ void k_zero_cnt() {
    int i = blockIdx.x * blockDim.x + threadIdx.x;
    if (i < NN) { g_cnt[i] = 0; g_fill[i] = 0; }
    if (i < 768) { g_sum[i] = 0.f; g_sumsq[i] = 0.f; }
}

__global__ void k_hist(const int* __restrict__ dst) {
    int e = blockIdx.x * blockDim.x + threadIdx.x;
    if (e < NE) atomicAdd(&g_cnt[dst[e]], 1);
}

__global__ void k_scan() {   // single block, 1024 threads, shuffle-based
    __shared__ int wsum[32];
    __shared__ int s_off;
    const int tid  = threadIdx.x;
    const int lane = tid & 31;
    const int wid  = tid >> 5;
    if (tid == 0) { s_off = 0; g_rowptr[0] = 0; }
    __syncthreads();
    for (int base = 0; base < NN; base += 1024) {
        int i = base + tid;
        int v = (i < NN) ? g_cnt[i] : 0;
        int x = v;
        #pragma unroll
        for (int d = 1; d < 32; d <<= 1) {
            int t = __shfl_up_sync(0xffffffffu, x, d);
            if (lane >= d) x += t;
        }
        if (lane == 31) wsum[wid] = x;
        __syncthreads();
        if (wid == 0) {
            int w = wsum[lane];
            #pragma unroll
            for (int d = 1; d < 32; d <<= 1) {
                int t = __shfl_up_sync(0xffffffffu, w, d);
                if (lane >= d) w += t;
            }
            wsum[lane] = w;
        }
        __syncthreads();
        int incl = x + (wid ? wsum[wid - 1] : 0);
        int off  = s_off;
        if (i < NN) {
            g_rowptr[i + 1] = off + incl;
            g_invdeg[i] = 1.0f / (float)max(v, 1);
        }
        __syncthreads();
        if (tid == 1023) s_off = off + incl;
        __syncthreads();
    }
}

__global__ void k_fill(const int* __restrict__ src, const int* __restrict__ dst) {
    int e = blockIdx.x * blockDim.x + threadIdx.x;
    if (e < NE) {
        int d = dst[e];
        int p = g_rowptr[d] + atomicAdd(&g_fill[d], 1);
        g_csr[p] = src[e];
    }
}

// ---------------- x -> fp16 convert ----------------
__global__ void k_cvtx(const float* __restrict__ x) {
    const int total = NN * 16;   // uint4 count
    int i = blockIdx.x * blockDim.x + threadIdx.x;
    if (i >= total) return;
    const float4* xp = reinterpret_cast<const float4*>(x);
    float4 a = xp[i * 2], b = xp[i * 2 + 1];
    uint4 o;
    __half2* op = (__half2*)&o;
    op[0] = __floats2half2_rn(a.x, a.y);
    op[1] = __floats2half2_rn(a.z, a.w);
    op[2] = __floats2half2_rn(b.x, b.y);
    op[3] = __floats2half2_rn(b.z, b.w);
    g_xh[i] = o;
}

// ---------------- mean aggregation (fp16 in, fp32 accum, fp16 out) ----------------
template<int DIN, bool FROMX>
__global__ void k_agg() {
    const int TPN = DIN / 8;     // uint4 lanes per node
    int t = blockIdx.x * blockDim.x + threadIdx.x;
    int node = t / TPN;
    if (node >= NN) return;
    int c8 = t % TPN;
    const uint4* __restrict__ hin = FROMX ? g_xh : g_hh;
    int beg = g_rowptr[node], end = g_rowptr[node + 1];
    float a0 = 0.f, a1 = 0.f, a2 = 0.f, a3 = 0.f;
    float a4 = 0.f, a5 = 0.f, a6 = 0.f, a7 = 0.f;
    for (int e = beg; e < end; e++) {
        int s = g_csr[e];
        uint4 u = hin[(size_t)s * TPN + c8];
        const __half2* hp = (const __half2*)&u;
        float2 f0 = __half22float2(hp[0]);
        float2 f1 = __half22float2(hp[1]);
        float2 f2 = __half22float2(hp[2]);
        float2 f3 = __half22float2(hp[3]);
        a0 += f0.x; a1 += f0.y; a2 += f1.x; a3 += f1.y;
        a4 += f2.x; a5 += f2.y; a6 += f3.x; a7 += f3.y;
    }
    float inv = g_invdeg[node];
    uint4 o;
    __half2* op = (__half2*)&o;
    op[0] = __floats2half2_rn(a0 * inv, a1 * inv);
    op[1] = __floats2half2_rn(a2 * inv, a3 * inv);
    op[2] = __floats2half2_rn(a4 * inv, a5 * inv);
    op[3] = __floats2half2_rn(a6 * inv, a7 * inv);
    g_mh[(size_t)node * TPN + c8] = o;
}

// ---------------- fused dual GEMM (TF32 tensor cores, fp16 A) + BN stats ----------------
// Block tile 128(M) x 64(N), 256 threads = 8 warps in 4x2, warp tile 32x32.
template<int K, int DOUT, bool FROMX>
__global__ __launch_bounds__(256) void k_gemm(
    const float* __restrict__ B1w, const float* __restrict__ B2w,
    const float* __restrict__ bias, int layer)
{
    __shared__ float As[128 * 20];   // [m][k], stride 20
    __shared__ float Bs[16 * 68];    // [k][n], stride 68

    const int tid    = threadIdx.x;
    const int lane   = tid & 31;
    const int wid    = tid >> 5;
    const int warp_m = wid >> 1;
    const int warp_n = wid & 1;
    const int mbase  = warp_m * 32;
    const int nbase  = warp_n * 32;
    const int n0 = blockIdx.x * 64;
    const int m0 = blockIdx.y * 128;

    const int a_row = tid >> 1;          // 0..127
    const int a_u4  = tid & 1;           // which uint4 (8 halves) in the 16-k chunk
    const int b_row = tid >> 4;          // 0..15
    const int b_col = (tid & 15) * 4;

    const int THK = K / 8;               // uint4 per row
    const uint4* A1 = g_mh;
    const uint4* A2 = FROMX ? g_xh : g_hh;
    float*       C  = (float*)g_pre;

    float acc[2][4][4];
    #pragma unroll
    for (int i = 0; i < 2; i++)
        #pragma unroll
        for (int j = 0; j < 4; j++)
            #pragma unroll
            for (int r = 0; r < 4; r++) acc[i][j][r] = 0.f;

    #pragma unroll
    for (int phase = 0; phase < 2; phase++) {
        const uint4* __restrict__ A = phase ? A2 : A1;
        const float* __restrict__ B = phase ? B2w : B1w;
        for (int k0 = 0; k0 < K; k0 += 16) {
            // stage A tile [128 x 16] from fp16 (exact in tf32)
            const int gr = m0 + a_row;
            uint4 u = (gr < NN) ? A[(size_t)gr * THK + (k0 >> 3) + a_u4]
                                : make_uint4(0u, 0u, 0u, 0u);
            const __half2* hp = (const __half2*)&u;
            float2 f0 = __half22float2(hp[0]);
            float2 f1 = __half22float2(hp[1]);
            float2 f2 = __half22float2(hp[2]);
            float2 f3 = __half22float2(hp[3]);
            float* ap = &As[a_row * 20 + a_u4 * 8];
            ap[0] = f0.x; ap[1] = f0.y; ap[2] = f1.x; ap[3] = f1.y;
            ap[4] = f2.x; ap[5] = f2.y; ap[6] = f3.x; ap[7] = f3.y;
            // stage B tile [16 x 64] (tf32-rounded)
            float4 bv = *reinterpret_cast<const float4*>(
                B + (size_t)(k0 + b_row) * DOUT + n0 + b_col);
            float* bp = &Bs[b_row * 68 + b_col];
            bp[0] = to_tf32(bv.x); bp[1] = to_tf32(bv.y);
            bp[2] = to_tf32(bv.z); bp[3] = to_tf32(bv.w);
            __syncthreads();

            const unsigned* Asu = (const unsigned*)As;
            const unsigned* Bsu = (const unsigned*)Bs;
            #pragma unroll
            for (int ks = 0; ks < 16; ks += 8) {
                unsigned af[2][4], bf[4][2];
                #pragma unroll
                for (int sm = 0; sm < 2; sm++) {
                    int r = mbase + sm * 16 + (lane >> 2);
                    int kk = ks + (lane & 3);
                    af[sm][0] = Asu[r * 20 + kk];
                    af[sm][1] = Asu[(r + 8) * 20 + kk];
                    af[sm][2] = Asu[r * 20 + kk + 4];
                    af[sm][3] = Asu[(r + 8) * 20 + kk + 4];
                }
                #pragma unroll
                for (int sn = 0; sn < 4; sn++) {
                    int cc = nbase + sn * 8 + (lane >> 2);
                    int kb = ks + (lane & 3);
                    bf[sn][0] = Bsu[kb * 68 + cc];
                    bf[sn][1] = Bsu[(kb + 4) * 68 + cc];
                }
                #pragma unroll
                for (int sm = 0; sm < 2; sm++)
                    #pragma unroll
                    for (int sn = 0; sn < 4; sn++)
                        mma_tf32(acc[sm][sn], af[sm], bf[sn]);
            }
            __syncthreads();
        }
    }

    // ---------------- epilogue: bias + store + BN partial sums ----------------
    #pragma unroll
    for (int sn = 0; sn < 4; sn++) {
        const int colg = n0 + nbase + sn * 8 + 2 * (lane & 3);
        const float bb0 = bias[colg];
        const float bb1 = bias[colg + 1];
        float s0 = 0.f, s1 = 0.f, q0 = 0.f, q1 = 0.f;
        #pragma unroll
        for (int sm = 0; sm < 2; sm++) {
            const int r0 = m0 + mbase + sm * 16 + (lane >> 2);
            const int r1 = r0 + 8;
            float v0 = acc[sm][sn][0] + bb0;
            float v1 = acc[sm][sn][1] + bb1;
            float v2 = acc[sm][sn][2] + bb0;
            float v3 = acc[sm][sn][3] + bb1;
            if (r0 < NN) {
                *reinterpret_cast<float2*>(C + (size_t)r0 * DOUT + colg) =
                    make_float2(v0, v1);
                s0 += v0; q0 += v0 * v0;
                s1 += v1; q1 += v1 * v1;
            }
            if (r1 < NN) {
                *reinterpret_cast<float2*>(C + (size_t)r1 * DOUT + colg) =
                    make_float2(v2, v3);
                s0 += v2; q0 += v2 * v2;
                s1 += v3; q1 += v3 * v3;
            }
        }
        #pragma unroll
        for (int d = 16; d >= 4; d >>= 1) {
            s0 += __shfl_down_sync(0xffffffffu, s0, d);
            s1 += __shfl_down_sync(0xffffffffu, s1, d);
            q0 += __shfl_down_sync(0xffffffffu, q0, d);
            q1 += __shfl_down_sync(0xffffffffu, q1, d);
        }
        if (lane < 4) {
            const int cg = n0 + nbase + sn * 8 + 2 * lane;
            atomicAdd(&g_sum  [layer * 256 + cg],     s0);
            atomicAdd(&g_sum  [layer * 256 + cg + 1], s1);
            atomicAdd(&g_sumsq[layer * 256 + cg],     q0);
            atomicAdd(&g_sumsq[layer * 256 + cg + 1], q1);
        }
    }
}

// ---------------- BN finalize + apply ----------------
template<int DOUT>
__global__ void k_bnfin(const float* __restrict__ gamma, const float* __restrict__ beta,
                        int layer) {
    int cidx = threadIdx.x;
    if (cidx < DOUT) {
        float mu  = g_sum[layer * 256 + cidx] * (1.0f / NN);
        float var = g_sumsq[layer * 256 + cidx] * (1.0f / NN) - mu * mu;
        float sc  = gamma[cidx] * rsqrtf(var + 1e-5f);
        ((float*)g_scale)[cidx] = sc;
        ((float*)g_shift)[cidx] = beta[cidx] - mu * sc;
    }
}

// BN + ReLU -> fp16 hidden buffer (layers 0,1)
template<int DOUT>
__global__ void k_bnapply_h() {
    const int total = NN * (DOUT / 8);
    int i = blockIdx.x * blockDim.x + threadIdx.x;
    if (i >= total) return;
    int c8 = i % (DOUT / 8);
    float4 v0 = g_pre[i * 2];
    float4 v1 = g_pre[i * 2 + 1];
    float4 sc0 = g_scale[c8 * 2], sc1 = g_scale[c8 * 2 + 1];
    float4 sh0 = g_shift[c8 * 2], sh1 = g_shift[c8 * 2 + 1];
    v0.x = fmaxf(v0.x * sc0.x + sh0.x, 0.f);
    v0.y = fmaxf(v0.y * sc0.y + sh0.y, 0.f);
    v0.z = fmaxf(v0.z * sc0.z + sh0.z, 0.f);
    v0.w = fmaxf(v0.w * sc0.w + sh0.w, 0.f);
    v1.x = fmaxf(v1.x * sc1.x + sh1.x, 0.f);
    v1.y = fmaxf(v1.y * sc1.y + sh1.y, 0.f);
    v1.z = fmaxf(v1.z * sc1.z + sh1.z, 0.f);
    v1.w = fmaxf(v1.w * sc1.w + sh1.w, 0.f);
    uint4 o;
    __half2* op = (__half2*)&o;
    op[0] = __floats2half2_rn(v0.x, v0.y);
    op[1] = __floats2half2_rn(v0.z, v0.w);
    op[2] = __floats2half2_rn(v1.x, v1.y);
    op[3] = __floats2half2_rn(v1.z, v1.w);
    g_hh[i] = o;
}

// BN (no ReLU) -> fp32 output (layer 2)
template<int DOUT>
__global__ void k_bnapply_out(float* __restrict__ outp) {
    const int total = NN * (DOUT / 4);
    int i = blockIdx.x * blockDim.x + threadIdx.x;
    if (i >= total) return;
    int c4 = i % (DOUT / 4);
    float4 v  = g_pre[i];
    float4 sc = g_scale[c4];
    float4 sh = g_shift[c4];
    v.x = v.x * sc.x + sh.x;
    v.y = v.y * sc.y + sh.y;
    v.z = v.z * sc.z + sh.z;
    v.w = v.w * sc.w + sh.w;
    reinterpret_cast<float4*>(outp)[i] = v;
}

// ---------------- launch ----------------
extern "C" void kernel_launch(void* const* d_in, const int* in_sizes, int n_in,
                              void* d_out, int out_size) {
    const float* x    = (const float*)d_in[0];
    const int*   ei   = (const int*)d_in[1];
    const int*   esrc = ei;
    const int*   edst = ei + NE;
    const float* wn0 = (const float*)d_in[2];
    const float* ws0 = (const float*)d_in[3];
    const float* b0  = (const float*)d_in[4];
    const float* g0  = (const float*)d_in[5];
    const float* be0 = (const float*)d_in[6];
    const float* wn1 = (const float*)d_in[7];
    const float* ws1 = (const float*)d_in[8];
    const float* b1  = (const float*)d_in[9];
    const float* g1  = (const float*)d_in[10];
    const float* be1 = (const float*)d_in[11];
    const float* wn2 = (const float*)d_in[12];
    const float* ws2 = (const float*)d_in[13];
    const float* b2  = (const float*)d_in[14];
    const float* g2  = (const float*)d_in[15];
    const float* be2 = (const float*)d_in[16];
    float* out = (float*)d_out;

    k_zero_cnt<<<(NN + 255) / 256, 256>>>();
    k_hist<<<(NE + 255) / 256, 256>>>(edst);
    k_scan<<<1, 1024>>>();
    k_fill<<<(NE + 255) / 256, 256>>>(esrc, edst);
    k_cvtx<<<(NN * 16 + 255) / 256, 256>>>(x);

    const int M_TILES = (NN + 127) / 128;

    // ---- layer 0: 128 -> 256 ----
    k_agg<128, true><<<(NN * 16 + 255) / 256, 256>>>();
    k_gemm<128, 256, true><<<dim3(4, M_TILES), 256>>>(wn0, ws0, b0, 0);
    k_bnfin<256><<<1, 256>>>(g0, be0, 0);
    k_bnapply_h<256><<<(NN * 32 + 255) / 256, 256>>>();

    // ---- layer 1: 256 -> 256 ----
    k_agg<256, false><<<(NN * 32 + 255) / 256, 256>>>();
    k_gemm<256, 256, false><<<dim3(4, M_TILES), 256>>>(wn1, ws1, b1, 1);
    k_bnfin<256><<<1, 256>>>(g1, be1, 1);
    k_bnapply_h<256><<<(NN * 32 + 255) / 256, 256>>>();

    // ---- layer 2: 256 -> 128 ----
    k_agg<256, false><<<(NN * 32 + 255) / 256, 256>>>();
    k_gemm<256, 128, false><<<dim3(2, M_TILES), 256>>>(wn2, ws2, b2, 2);
    k_bnfin<128><<<1, 256>>>(g2, be2, 2);
    k_bnapply_out<128><<<(NN * 32 + 255) / 256, 256>>>(out);
}

// round 7
// speedup vs baseline: 2.0394x; 1.0724x over previous
#include <cuda_runtime.h>
#include <cuda_fp16.h>
#include <cstdint>

#define NN 50000
#define NE 800000

// ---------------- static device scratch ----------------
__device__ int    g_cnt[NN];
__device__ int    g_fill[NN];
__device__ int    g_rowptr[NN + 1];
__device__ float  g_invdeg[NN];
__device__ int    g_csr[NE];
__device__ uint4  g_xh[(size_t)NN * 16];   // x as fp16 (128 cols = 16 uint4)
__device__ uint4  g_hh[(size_t)NN * 32];   // hidden activations fp16 (<=256 cols)
__device__ uint4  g_mh[(size_t)NN * 32];   // aggregated mean fp16
__device__ float4 g_pre[(size_t)NN * 64];  // pre-BN linear output fp32
__device__ __half g_wh[262144];            // all 6 weights, fp16, [D][K] transposed
__device__ float  g_sum[768];              // 3 layers x 256
__device__ float  g_sumsq[768];
__device__ float4 g_scale[64];
__device__ float4 g_shift[64];

#define OFF_WN0 0
#define OFF_WS0 32768
#define OFF_WN1 65536
#define OFF_WS1 131072
#define OFF_WN2 196608
#define OFF_WS2 229376

// ---------------- helpers ----------------
__device__ __forceinline__ void mma_fp16(float* c, const unsigned* a, const unsigned* b) {
    asm("mma.sync.aligned.m16n8k16.row.col.f32.f16.f16.f32 "
        "{%0,%1,%2,%3}, {%4,%5,%6,%7}, {%8,%9}, {%0,%1,%2,%3};"
        : "+f"(c[0]), "+f"(c[1]), "+f"(c[2]), "+f"(c[3])
        : "r"(a[0]), "r"(a[1]), "r"(a[2]), "r"(a[3]),
          "r"(b[0]), "r"(b[1]));
}

// ---------------- CSR build ----------------
__global__ void k_zero_cnt() {
    int i = blockIdx.x * blockDim.x + threadIdx.x;
    if (i < NN) { g_cnt[i] = 0; g_fill[i] = 0; }
    if (i < 768) { g_sum[i] = 0.f; g_sumsq[i] = 0.f; }
}

__global__ void k_hist(const int* __restrict__ dst) {
    int e = blockIdx.x * blockDim.x + threadIdx.x;
    if (e < NE) atomicAdd(&g_cnt[dst[e]], 1);
}

__global__ void k_scan() {
    __shared__ int wsum[32];
    __shared__ int s_off;
    const int tid  = threadIdx.x;
    const int lane = tid & 31;
    const int wid  = tid >> 5;
    if (tid == 0) { s_off = 0; g_rowptr[0] = 0; }
    __syncthreads();
    for (int base = 0; base < NN; base += 1024) {
        int i = base + tid;
        int v = (i < NN) ? g_cnt[i] : 0;
        int x = v;
        #pragma unroll
        for (int d = 1; d < 32; d <<= 1) {
            int t = __shfl_up_sync(0xffffffffu, x, d);
            if (lane >= d) x += t;
        }
        if (lane == 31) wsum[wid] = x;
        __syncthreads();
        if (wid == 0) {
            int w = wsum[lane];
            #pragma unroll
            for (int d = 1; d < 32; d <<= 1) {
                int t = __shfl_up_sync(0xffffffffu, w, d);
                if (lane >= d) w += t;
            }
            wsum[lane] = w;
        }
        __syncthreads();
        int incl = x + (wid ? wsum[wid - 1] : 0);
        int off  = s_off;
        if (i < NN) {
            g_rowptr[i + 1] = off + incl;
            g_invdeg[i] = 1.0f / (float)max(v, 1);
        }
        __syncthreads();
        if (tid == 1023) s_off = off + incl;
        __syncthreads();
    }
}

__global__ void k_fill(const int* __restrict__ src, const int* __restrict__ dst) {
    int e = blockIdx.x * blockDim.x + threadIdx.x;
    if (e < NE) {
        int d = dst[e];
        int p = g_rowptr[d] + atomicAdd(&g_fill[d], 1);
        g_csr[p] = src[e];
    }
}

// ---------------- x -> fp16 convert ----------------
__global__ void k_cvtx(const float* __restrict__ x) {
    const int total = NN * 16;
    int i = blockIdx.x * blockDim.x + threadIdx.x;
    if (i >= total) return;
    const float4* xp = reinterpret_cast<const float4*>(x);
    float4 a = xp[i * 2], b = xp[i * 2 + 1];
    uint4 o;
    __half2* op = (__half2*)&o;
    op[0] = __floats2half2_rn(a.x, a.y);
    op[1] = __floats2half2_rn(a.z, a.w);
    op[2] = __floats2half2_rn(b.x, b.y);
    op[3] = __floats2half2_rn(b.z, b.w);
    g_xh[i] = o;
}

// ---------------- weight transpose + fp16 convert: [K][D] f32 -> [D][K] f16 ----------------
__global__ void k_cvtw(const float* __restrict__ w, int K, int D, int off) {
    __shared__ float t[32][33];
    const int d0 = blockIdx.x * 32, k0 = blockIdx.y * 32;
    const int tx = threadIdx.x, ty = threadIdx.y;
    #pragma unroll
    for (int i = ty; i < 32; i += 8)
        t[i][tx] = w[(size_t)(k0 + i) * D + d0 + tx];
    __syncthreads();
    #pragma unroll
    for (int i = ty; i < 32; i += 8)
        g_wh[off + (size_t)(d0 + i) * K + k0 + tx] = __float2half_rn(t[tx][i]);
}

// ---------------- mean aggregation (fp16 in, fp32 accum, fp16 out) ----------------
template<int DIN, bool FROMX>
__global__ void k_agg() {
    const int TPN = DIN / 8;
    int t = blockIdx.x * blockDim.x + threadIdx.x;
    int node = t / TPN;
    if (node >= NN) return;
    int c8 = t % TPN;
    const uint4* __restrict__ hin = FROMX ? g_xh : g_hh;
    int beg = g_rowptr[node], end = g_rowptr[node + 1];
    float a0 = 0.f, a1 = 0.f, a2 = 0.f, a3 = 0.f;
    float a4 = 0.f, a5 = 0.f, a6 = 0.f, a7 = 0.f;
    for (int e = beg; e < end; e++) {
        int s = g_csr[e];
        uint4 u = hin[(size_t)s * TPN + c8];
        const __half2* hp = (const __half2*)&u;
        float2 f0 = __half22float2(hp[0]);
        float2 f1 = __half22float2(hp[1]);
        float2 f2 = __half22float2(hp[2]);
        float2 f3 = __half22float2(hp[3]);
        a0 += f0.x; a1 += f0.y; a2 += f1.x; a3 += f1.y;
        a4 += f2.x; a5 += f2.y; a6 += f3.x; a7 += f3.y;
    }
    float inv = g_invdeg[node];
    uint4 o;
    __half2* op = (__half2*)&o;
    op[0] = __floats2half2_rn(a0 * inv, a1 * inv);
    op[1] = __floats2half2_rn(a2 * inv, a3 * inv);
    op[2] = __floats2half2_rn(a4 * inv, a5 * inv);
    op[3] = __floats2half2_rn(a6 * inv, a7 * inv);
    g_mh[(size_t)node * TPN + c8] = o;
}

// ---------------- fused dual GEMM (fp16 HMMA, fp32 accum) + BN stats ----------------
template<int K, int DOUT, bool FROMX>
__global__ __launch_bounds__(256) void k_gemm(
    int off1, int off2, const float* __restrict__ bias, int layer)
{
    __shared__ unsigned As2[128 * 10];   // half2 [m][k-pair], stride 10
    __shared__ unsigned Bs2[64 * 10];    // half2 [n][k-pair], stride 10

    const int tid    = threadIdx.x;
    const int lane   = tid & 31;
    const int wid    = tid >> 5;
    const int warp_m = wid >> 1;
    const int warp_n = wid & 1;
    const int mbase  = warp_m * 32;
    const int nbase  = warp_n * 32;
    const int n0 = blockIdx.x * 64;
    const int m0 = blockIdx.y * 128;

    const int a_row = tid >> 1;
    const int a_u4  = tid & 1;
    const int b_n   = tid >> 1;
    const int b_u4  = tid & 1;

    const int THK = K / 8;
    const uint4* A1 = g_mh;
    const uint4* A2 = FROMX ? g_xh : g_hh;
    const __half* B1w = g_wh + off1;
    const __half* B2w = g_wh + off2;
    float*       C  = (float*)g_pre;

    float acc[2][4][4];
    #pragma unroll
    for (int i = 0; i < 2; i++)
        #pragma unroll
        for (int j = 0; j < 4; j++)
            #pragma unroll
            for (int r = 0; r < 4; r++) acc[i][j][r] = 0.f;

    #pragma unroll
    for (int phase = 0; phase < 2; phase++) {
        const uint4* __restrict__ A = phase ? A2 : A1;
        const __half* __restrict__ B = phase ? B2w : B1w;
        for (int k0 = 0; k0 < K; k0 += 16) {
            {
                const int gr = m0 + a_row;
                uint4 u = (gr < NN) ? A[(size_t)gr * THK + (k0 >> 3) + a_u4]
                                    : make_uint4(0u, 0u, 0u, 0u);
                unsigned* ap = &As2[a_row * 10 + a_u4 * 4];
                ap[0] = u.x; ap[1] = u.y; ap[2] = u.z; ap[3] = u.w;
            }
            if (b_n < 64) {
                uint4 u = *reinterpret_cast<const uint4*>(
                    B + (size_t)(n0 + b_n) * K + k0 + b_u4 * 8);
                unsigned* bp = &Bs2[b_n * 10 + b_u4 * 4];
                bp[0] = u.x; bp[1] = u.y; bp[2] = u.z; bp[3] = u.w;
            }
            __syncthreads();

            #pragma unroll
            for (int sm = 0; sm < 2; sm++) {
                const int r = mbase + sm * 16 + (lane >> 2);
                unsigned af[4];
                af[0] = As2[r * 10 + (lane & 3)];
                af[1] = As2[(r + 8) * 10 + (lane & 3)];
                af[2] = As2[r * 10 + (lane & 3) + 4];
                af[3] = As2[(r + 8) * 10 + (lane & 3) + 4];
                #pragma unroll
                for (int sn = 0; sn < 4; sn++) {
                    const int cc = nbase + sn * 8 + (lane >> 2);
                    unsigned bf[2];
                    bf[0] = Bs2[cc * 10 + (lane & 3)];
                    bf[1] = Bs2[cc * 10 + (lane & 3) + 4];
                    mma_fp16(acc[sm][sn], af, bf);
                }
            }
            __syncthreads();
        }
    }

    #pragma unroll
    for (int sn = 0; sn < 4; sn++) {
        const int colg = n0 + nbase + sn * 8 + 2 * (lane & 3);
        const float bb0 = bias[colg];
        const float bb1 = bias[colg + 1];
        float s0 = 0.f, s1 = 0.f, q0 = 0.f, q1 = 0.f;
        #pragma unroll
        for (int sm = 0; sm < 2; sm++) {
            const int r0 = m0 + mbase + sm * 16 + (lane >> 2);
            const int r1 = r0 + 8;
            float v0 = acc[sm][sn][0] + bb0;
            float v1 = acc[sm][sn][1] + bb1;
            float v2 = acc[sm][sn][2] + bb0;
            float v3 = acc[sm][sn][3] + bb1;
            if (r0 < NN) {
                *reinterpret_cast<float2*>(C + (size_t)r0 * DOUT + colg) =
                    make_float2(v0, v1);
                s0 += v0; q0 += v0 * v0;
                s1 += v1; q1 += v1 * v1;
            }
            if (r1 < NN) {
                *reinterpret_cast<float2*>(C + (size_t)r1 * DOUT + colg) =
                    make_float2(v2, v3);
                s0 += v2; q0 += v2 * v2;
                s1 += v3; q1 += v3 * v3;
            }
        }
        #pragma unroll
        for (int d = 16; d >= 4; d >>= 1) {
            s0 += __shfl_down_sync(0xffffffffu, s0, d);
            s1 += __shfl_down_sync(0xffffffffu, s1, d);
            q0 += __shfl_down_sync(0xffffffffu, q0, d);
            q1 += __shfl_down_sync(0xffffffffu, q1, d);
        }
        if (lane < 4) {
            const int cg = n0 + nbase + sn * 8 + 2 * lane;
            atomicAdd(&g_sum  [layer * 256 + cg],     s0);
            atomicAdd(&g_sum  [layer * 256 + cg + 1], s1);
            atomicAdd(&g_sumsq[layer * 256 + cg],     q0);
            atomicAdd(&g_sumsq[layer * 256 + cg + 1], q1);
        }
    }
}

// ---------------- BN finalize + apply ----------------
template<int DOUT>
__global__ void k_bnfin(const float* __restrict__ gamma, const float* __restrict__ beta,
                        int layer) {
    int cidx = threadIdx.x;
    if (cidx < DOUT) {
        float mu  = g_sum[layer * 256 + cidx] * (1.0f / NN);
        float var = g_sumsq[layer * 256 + cidx] * (1.0f / NN) - mu * mu;
        float sc  = gamma[cidx] * rsqrtf(var + 1e-5f);
        ((float*)g_scale)[cidx] = sc;
        ((float*)g_shift)[cidx] = beta[cidx] - mu * sc;
    }
}

template<int DOUT>
__global__ void k_bnapply_h() {
    const int total = NN * (DOUT / 8);
    int i = blockIdx.x * blockDim.x + threadIdx.x;
    if (i >= total) return;
    int c8 = i % (DOUT / 8);
    float4 v0 = g_pre[i * 2];
    float4 v1 = g_pre[i * 2 + 1];
    float4 sc0 = g_scale[c8 * 2], sc1 = g_scale[c8 * 2 + 1];
    float4 sh0 = g_shift[c8 * 2], sh1 = g_shift[c8 * 2 + 1];
    v0.x = fmaxf(v0.x * sc0.x + sh0.x, 0.f);
    v0.y = fmaxf(v0.y * sc0.y + sh0.y, 0.f);
    v0.z = fmaxf(v0.z * sc0.z + sh0.z, 0.f);
    v0.w = fmaxf(v0.w * sc0.w + sh0.w, 0.f);
    v1.x = fmaxf(v1.x * sc1.x + sh1.x, 0.f);
    v1.y = fmaxf(v1.y * sc1.y + sh1.y, 0.f);
    v1.z = fmaxf(v1.z * sc1.z + sh1.z, 0.f);
    v1.w = fmaxf(v1.w * sc1.w + sh1.w, 0.f);
    uint4 o;
    __half2* op = (__half2*)&o;
    op[0] = __floats2half2_rn(v0.x, v0.y);
    op[1] = __floats2half2_rn(v0.z, v0.w);
    op[2] = __floats2half2_rn(v1.x, v1.y);
    op[3] = __floats2half2_rn(v1.z, v1.w);
    g_hh[i] = o;
}

template<int DOUT>
__global__ void k_bnapply_out(float* __restrict__ outp) {
    const int total = NN * (DOUT / 4);
    int i = blockIdx.x * blockDim.x + threadIdx.x;
    if (i >= total) return;
    int c4 = i % (DOUT / 4);
    float4 v  = g_pre[i];
    float4 sc = g_scale[c4];
    float4 sh = g_shift[c4];
    v.x = v.x * sc.x + sh.x;
    v.y = v.y * sc.y + sh.y;
    v.z = v.z * sc.z + sh.z;
    v.w = v.w * sc.w + sh.w;
    reinterpret_cast<float4*>(outp)[i] = v;
}

// ---------------- launch ----------------
extern "C" void kernel_launch(void* const* d_in, const int* in_sizes, int n_in,
                              void* d_out, int out_size) {
    const float* x    = (const float*)d_in[0];
    const int*   ei   = (const int*)d_in[1];
    const int*   esrc = ei;
    const int*   edst = ei + NE;
    const float* wn0 = (const float*)d_in[2];
    const float* ws0 = (const float*)d_in[3];
    const float* b0  = (const float*)d_in[4];
    const float* g0  = (const float*)d_in[5];
    const float* be0 = (const float*)d_in[6];
    const float* wn1 = (const float*)d_in[7];
    const float* ws1 = (const float*)d_in[8];
    const float* b1  = (const float*)d_in[9];
    const float* g1  = (const float*)d_in[10];
    const float* be1 = (const float*)d_in[11];
    const float* wn2 = (const float*)d_in[12];
    const float* ws2 = (const float*)d_in[13];
    const float* b2  = (const float*)d_in[14];
    const float* g2  = (const float*)d_in[15];
    const float* be2 = (const float*)d_in[16];
    float* out = (float*)d_out;

    k_zero_cnt<<<(NN + 255) / 256, 256>>>();
    k_hist<<<(NE + 255) / 256, 256>>>(edst);
    k_scan<<<1, 1024>>>();
    k_fill<<<(NE + 255) / 256, 256>>>(esrc, edst);
    k_cvtx<<<(NN * 16 + 255) / 256, 256>>>(x);

    dim3 tb(32, 8);
    k_cvtw<<<dim3(8, 4), tb>>>(wn0, 128, 256, OFF_WN0);
    k_cvtw<<<dim3(8, 4), tb>>>(ws0, 128, 256, OFF_WS0);
    k_cvtw<<<dim3(8, 8), tb>>>(wn1, 256, 256, OFF_WN1);
    k_cvtw<<<dim3(8, 8), tb>>>(ws1, 256, 256, OFF_WS1);
    k_cvtw<<<dim3(4, 8), tb>>>(wn2, 256, 128, OFF_WN2);
    k_cvtw<<<dim3(4, 8), tb>>>(ws2, 256, 128, OFF_WS2);

    const int M_TILES = (NN + 127) / 128;

    // ---- layer 0: 128 -> 256 ----
    k_agg<128, true><<<(NN * 16 + 255) / 256, 256>>>();
    k_gemm<128, 256, true><<<dim3(4, M_TILES), 256>>>(OFF_WN0, OFF_WS0, b0, 0);
    k_bnfin<256><<<1, 256>>>(g0, be0, 0);
    k_bnapply_h<256><<<(NN * 32 + 255) / 256, 256>>>();

    // ---- layer 1: 256 -> 256 ----
    k_agg<256, false><<<(NN * 32 + 255) / 256, 256>>>();
    k_gemm<256, 256, false><<<dim3(4, M_TILES), 256>>>(OFF_WN1, OFF_WS1, b1, 1);
    k_bnfin<256><<<1, 256>>>(g1, be1, 1);
    k_bnapply_h<256><<<(NN * 32 + 255) / 256, 256>>>();

    // ---- layer 2: 256 -> 128 ----
    k_agg<256, false><<<(NN * 32 + 255) / 256, 256>>>();
    k_gemm<256, 128, false><<<dim3(2, M_TILES), 256>>>(OFF_WN2, OFF_WS2, b2, 2);
    k_bnfin<128><<<1, 256>>>(g2, be2, 2);
    k_bnapply_out<128><<<(NN * 32 + 255) / 256, 256>>>(out);
}